// round 11
// baseline (speedup 1.0000x reference)
#include <cuda_runtime.h>
#include <cuda_fp16.h>
#include <cstdint>
#include <math.h>

#define NB 8
#define NN 2048
#define DD 128
#define ALPHA 0.2f
#define PPAD 68

// ------------------------- device scratch ----------------------------------
__device__ __align__(16) unsigned short g_WhT_hi[NB * DD * NN];  // [b][d][j] fp16 hi
__device__ __align__(16) unsigned short g_WhT_lo[NB * DD * NN];  // [b][d][j] fp16 lo
__device__ __align__(16) float4 g_row4[NB * NN];  // (es, exp(es), exp(.2es), 0)
__device__ __align__(16) float4 g_col4[NB * NN];  // (ed, exp(ed), exp(.2ed), 0)

// ------------------------- helpers -----------------------------------------
__device__ __forceinline__ uint32_t smem_u32(const void* p) {
    uint32_t a;
    asm("{ .reg .u64 t; cvta.to.shared.u64 t, %1; cvt.u32.u64 %0, t; }" : "=r"(a) : "l"(p));
    return a;
}
#define SW128(o) ((o) ^ (((o) >> 3) & 0x70))

__device__ __forceinline__ void ldm_x4(uint32_t* r, uint32_t addr) {
    asm volatile("ldmatrix.sync.aligned.m8n8.x4.shared.b16 {%0,%1,%2,%3}, [%4];"
                 : "=r"(r[0]), "=r"(r[1]), "=r"(r[2]), "=r"(r[3]) : "r"(addr));
}
__device__ __forceinline__ void mma_f16(float* c, const uint32_t* a, const uint32_t* b) {
    asm volatile("mma.sync.aligned.m16n8k16.row.col.f32.f16.f16.f32 "
                 "{%0,%1,%2,%3}, {%4,%5,%6,%7}, {%8,%9}, {%0,%1,%2,%3};"
                 : "+f"(c[0]), "+f"(c[1]), "+f"(c[2]), "+f"(c[3])
                 : "r"(a[0]), "r"(a[1]), "r"(a[2]), "r"(a[3]), "r"(b[0]), "r"(b[1]));
}

#define CP_ASYNC16(dst, src) \
    asm volatile("cp.async.cg.shared.global [%0], [%1], 16;" :: "r"(dst), "l"(src) : "memory")
#define CP_COMMIT()  asm volatile("cp.async.commit_group;" ::: "memory")
#define CP_WAIT0()   asm volatile("cp.async.wait_group 0;" ::: "memory")

// ---- f32x2 helpers ---------------------------------------------------------
__device__ __forceinline__ void ffma2(unsigned long long& acc,
                                      unsigned long long a, unsigned long long b) {
    asm("fma.rn.f32x2 %0, %1, %2, %0;" : "+l"(acc) : "l"(a), "l"(b));
}
__device__ __forceinline__ unsigned long long pack2(float x, float y) {
    unsigned long long r;
    asm("mov.b64 %0, {%1, %2};" : "=l"(r) : "f"(x), "f"(y));
    return r;
}
__device__ __forceinline__ void unpack2(float& lo, float& hi, unsigned long long v) {
    asm("mov.b64 {%0, %1}, %2;" : "=f"(lo), "=f"(hi) : "l"(v));
}

// ---------------------------------------------------------------------------
// Kernel A: Wh = h @ W (FFMA2 GEMM, 64 rows/block), fused:
//   - fp16 hi/lo split of Wh^T -> g_WhT_hi/lo [b][d][j]
//   - g_row4/g_col4 factorized exp tables
// ---------------------------------------------------------------------------
#define SMEM_A (128*128*4 + 128*PPAD*4)

__global__ __launch_bounds__(256) void wh_gemm_kernel(
    const float* __restrict__ h, const float* __restrict__ W,
    const float* __restrict__ a_src, const float* __restrict__ a_dst)
{
    extern __shared__ __align__(16) char smem_raw[];
    float* Ws = (float*)smem_raw;               // [k][d] 128x128
    float* hs = Ws + 128 * 128;                 // [k][row] 128xPPAD

    int t = threadIdx.x;
    int r0blk = blockIdx.x * 64;

    {
        const float4* src = (const float4*)W;
        float4* dst = (float4*)Ws;
#pragma unroll
        for (int q = 0; q < 16; ++q) dst[t + q * 256] = src[t + q * 256];
    }
#pragma unroll
    for (int q = 0; q < 32; ++q) {
        int idx = t + q * 256;
        int k = idx & 127, row = idx >> 7;
        hs[k * PPAD + row] = h[(size_t)(r0blk + row) * DD + k];
    }
    __syncthreads();

    int tx = t & 15, ty = t >> 4;
    int d0 = tx * 8;

    unsigned long long acc[4][4];
#pragma unroll
    for (int r = 0; r < 4; ++r)
#pragma unroll
        for (int c = 0; c < 4; ++c) acc[r][c] = 0ull;

#pragma unroll 4
    for (int k = 0; k < 128; ++k) {
        float4 hv = *(const float4*)&hs[k * PPAD + ty * 4];
        ulonglong2 w0 = *(const ulonglong2*)&Ws[k * 128 + d0];
        ulonglong2 w1 = *(const ulonglong2*)&Ws[k * 128 + d0 + 4];
        unsigned long long pp[4];
        pp[0] = pack2(hv.x, hv.x); pp[1] = pack2(hv.y, hv.y);
        pp[2] = pack2(hv.z, hv.z); pp[3] = pack2(hv.w, hv.w);
#pragma unroll
        for (int r = 0; r < 4; ++r) {
            ffma2(acc[r][0], pp[r], w0.x);
            ffma2(acc[r][1], pp[r], w0.y);
            ffma2(acc[r][2], pp[r], w1.x);
            ffma2(acc[r][3], pp[r], w1.y);
        }
    }

    float asv[8], adv[8];
    {
        float4 s0 = *(const float4*)&a_src[d0];
        float4 s1 = *(const float4*)&a_src[d0 + 4];
        float4 t0 = *(const float4*)&a_dst[d0];
        float4 t1 = *(const float4*)&a_dst[d0 + 4];
        asv[0]=s0.x; asv[1]=s0.y; asv[2]=s0.z; asv[3]=s0.w;
        asv[4]=s1.x; asv[5]=s1.y; asv[6]=s1.z; asv[7]=s1.w;
        adv[0]=t0.x; adv[1]=t0.y; adv[2]=t0.z; adv[3]=t0.w;
        adv[4]=t1.x; adv[5]=t1.y; adv[6]=t1.z; adv[7]=t1.w;
    }

#pragma unroll
    for (int r = 0; r < 4; ++r) {
        int row = r0blk + ty * 4 + r;
        float w[8];
        unpack2(w[0], w[1], acc[r][0]); unpack2(w[2], w[3], acc[r][1]);
        unpack2(w[4], w[5], acc[r][2]); unpack2(w[6], w[7], acc[r][3]);
        float sa = 0.f, sd = 0.f;
#pragma unroll
        for (int c = 0; c < 8; ++c) { sa = fmaf(w[c], asv[c], sa); sd = fmaf(w[c], adv[c], sd); }
#pragma unroll
        for (int off = 8; off > 0; off >>= 1) {
            sa += __shfl_xor_sync(0xffffffffu, sa, off);
            sd += __shfl_xor_sync(0xffffffffu, sd, off);
        }
        if (tx == 0) {
            g_row4[row] = make_float4(sa, __expf(sa), __expf(ALPHA * sa), 0.f);
            g_col4[row] = make_float4(sd, __expf(sd), __expf(ALPHA * sd), 0.f);
        }
    }

    // ---- transpose + fp16 hi/lo split staging (reuse hs region) ----
    __syncthreads();
    unsigned short* sthi = (unsigned short*)hs;          // [128 d][64 j]
    unsigned short* stlo = sthi + 128 * 64;
#pragma unroll
    for (int r = 0; r < 4; ++r) {
        float w[8];
        unpack2(w[0], w[1], acc[r][0]); unpack2(w[2], w[3], acc[r][1]);
        unpack2(w[4], w[5], acc[r][2]); unpack2(w[6], w[7], acc[r][3]);
        int jl = ty * 4 + r;
#pragma unroll
        for (int c = 0; c < 8; ++c) {
            __half hv = __float2half_rn(w[c]);
            float hf = __half2float(hv);
            __half lv = __float2half_rn(w[c] - hf);
            sthi[(d0 + c) * 64 + jl] = __half_as_ushort(hv);
            stlo[(d0 + c) * 64 + jl] = __half_as_ushort(lv);
        }
    }
    __syncthreads();

    int b = r0blk >> 11;
    int jblk = r0blk & (NN - 1);
    const uint4* s4h = (const uint4*)sthi;
    const uint4* s4l = (const uint4*)stlo;
    uint4* gh = (uint4*)g_WhT_hi;
    uint4* gl = (uint4*)g_WhT_lo;
#pragma unroll
    for (int q = 0; q < 4; ++q) {
        int idx = t + 256 * q;
        int d = idx >> 3, ch = idx & 7;
        size_t dst = (size_t)(b * DD + d) * 256 + (jblk >> 3) + ch;
        gh[dst] = s4h[idx];
        gl[dst] = s4l[idx];
    }
}

// ---------------------------------------------------------------------------
// Kernel B: pipelined HMMA fp16x2 aggregation. Grid (16, 8), 512 threads.
//  Block tile 128 i x 128 d; warp grid 4(i) x 4(d); warp tile 32 i x 32 d.
//  P fp16 (single) double-buffered; V hi/lo fp16 double-buffered (cp.async).
//  out = P*Vhi + P*Vlo (A-frags shared between the two GEMMs).
// ---------------------------------------------------------------------------
#define SM_COL4 0            // 32768 B
#define SM_P    32768        // + buf*16384
#define SM_V    65536        // + buf*32768 : Vhi at +0, Vlo at +16384
#define SM_L    131072       // 128 floats
#define SMEM_B_TOTAL 131584

__global__ __launch_bounds__(512, 1) void attn_mma_kernel(
    const int* __restrict__ adj, float* __restrict__ out)
{
    extern __shared__ __align__(1024) char sm[];
    uint32_t smb = smem_u32(sm);
    int t = threadIdx.x, wid = t >> 5, lane = t & 31;
    int b = blockIdx.y;
    int i0 = blockIdx.x * 128;
    int wy = wid & 3, wx = wid >> 2;

    // col factor table for this batch
    {
        const float4* src = g_col4 + b * NN;
        float4* dst = (float4*)(sm + SM_COL4);
#pragma unroll
        for (int q = 0; q < 4; ++q) dst[t + 512 * q] = src[t + 512 * q];
    }

    int i = t >> 2, qj = t & 3;        // fillP: row i, j-quarter (16 j each)
    float4 rv = g_row4[b * NN + i0 + i];
    float esi = rv.x, Ai = rv.y, Ci = rv.z;
    const int* __restrict__ adjrow = adj + (size_t)(i0 + i) * NN;
    const float4* col4 = (const float4*)(sm + SM_COL4);
    const uint4* vhi_g = (const uint4*)g_WhT_hi + (size_t)b * DD * 256;
    const uint4* vlo_g = (const uint4*)g_WhT_lo + (size_t)b * DD * 256;
    float lsum = 0.f;

    __syncthreads();   // col4 ready

    float acc[2][4][4];
#pragma unroll
    for (int m = 0; m < 2; ++m)
#pragma unroll
        for (int n = 0; n < 4; ++n)
#pragma unroll
            for (int q = 0; q < 4; ++q) acc[m][n][q] = 0.f;

    int grp = lane >> 3, lrow = lane & 7;

    // ---- pipeline helpers ----
    auto loadV = [&](int c, int buf) {
        uint32_t vbase = smb + SM_V + buf * 32768;
        int j8 = (c * 64) >> 3;
#pragma unroll
        for (int q = 0; q < 2; ++q) {
            int idx = t + 512 * q;              // 0..1023
            int d = idx >> 3, ch = idx & 7;     // d 0..127
            uint32_t off = SW128((uint32_t)(d * 128 + ch * 16));
            CP_ASYNC16(vbase + off,         (const char*)(vhi_g + d * 256 + j8 + ch));
            CP_ASYNC16(vbase + 16384 + off, (const char*)(vlo_g + d * 256 + j8 + ch));
        }
    };
    auto loadAdj = [&](int c, int4* am) {
        const int4* arow4 = (const int4*)(adjrow + c * 64 + qj * 16);
#pragma unroll
        for (int u = 0; u < 4; ++u) am[u] = __ldg(arow4 + u);
    };
    auto fillP = [&](int c, int buf, const int4* am) {
        int j0 = c * 64;
        char* ph_base = sm + SM_P + buf * 16384;
#pragma unroll
        for (int g = 0; g < 2; ++g) {           // 8 j per uint4 group
            uint32_t hw[4];
#pragma unroll
            for (int pr = 0; pr < 4; ++pr) {
                int jj = g * 8 + pr * 2;        // local 0..15
                int jg = j0 + qj * 16 + jj;
                int a0, a1;
                {
                    int4 av = am[jj >> 2];
                    if ((jj & 3) == 0) { a0 = av.x; a1 = av.y; }
                    else               { a0 = av.z; a1 = av.w; }
                }
                float4 c0 = col4[jg];
                float4 c1 = col4[jg + 1];
                float s0 = esi + c0.x;
                float s1 = esi + c1.x;
                float v0 = (s0 > 0.f) ? Ai * c0.y : Ci * c0.z;
                float v1 = (s1 > 0.f) ? Ai * c1.y : Ci * c1.z;
                float p0 = (a0 > 0) ? v0 : 0.f;
                float p1 = (a1 > 0) ? v1 : 0.f;
                lsum += p0 + p1;
                __half2 hh = __floats2half2_rn(p0, p1);   // p0 -> low half (j even)
                hw[pr] = *reinterpret_cast<uint32_t*>(&hh);
            }
            uint32_t off = SW128((uint32_t)(i * 128 + qj * 32 + g * 16));
            *(uint4*)(ph_base + off) = make_uint4(hw[0], hw[1], hw[2], hw[3]);
        }
    };

    // ---- prologue: fill buffer 0 ----
    int4 am[4];
    loadV(0, 0); CP_COMMIT();
    loadAdj(0, am);
    fillP(0, 0, am);
    CP_WAIT0();
    __syncthreads();

    // ---- main pipelined loop ----
    for (int c = 0; c < 32; ++c) {
        int cb = c & 1, nb = cb ^ 1;

        if (c < 31) {
            loadV(c + 1, nb); CP_COMMIT();
            loadAdj(c + 1, am);
        }

        // MMA on buffer cb
        {
            uint32_t phb = smb + SM_P + cb * 16384;
            uint32_t vhb = smb + SM_V + cb * 32768;
            uint32_t vlb = vhb + 16384;
#pragma unroll
            for (int ks = 0; ks < 4; ++ks) {
                uint32_t ah[2][4];
#pragma unroll
                for (int mt = 0; mt < 2; ++mt) {
                    int arow = wy * 32 + mt * 16 + (grp & 1) * 8 + lrow;
                    uint32_t aoff = SW128((uint32_t)(arow * 128 + ks * 32 + (grp >> 1) * 16));
                    ldm_x4(ah[mt], phb + aoff);
                }
#pragma unroll
                for (int np = 0; np < 2; ++np) {
                    int brow = wx * 32 + np * 16 + (grp >> 1) * 8 + lrow;
                    uint32_t boff = SW128((uint32_t)(brow * 128 + ks * 32 + (grp & 1) * 16));
                    uint32_t bh[4], bl[4];
                    ldm_x4(bh, vhb + boff);
                    ldm_x4(bl, vlb + boff);
#pragma unroll
                    for (int mt = 0; mt < 2; ++mt) {
                        mma_f16(acc[mt][np * 2],     ah[mt], bh);
                        mma_f16(acc[mt][np * 2 + 1], ah[mt], bh + 2);
                        mma_f16(acc[mt][np * 2],     ah[mt], bl);
                        mma_f16(acc[mt][np * 2 + 1], ah[mt], bl + 2);
                    }
                }
            }
        }

        if (c < 31) fillP(c + 1, nb, am);
        CP_WAIT0();
        __syncthreads();
    }

    // ---- row sums -> smem (4 threads per row) ----
    {
        lsum += __shfl_xor_sync(0xffffffffu, lsum, 1);
        lsum += __shfl_xor_sync(0xffffffffu, lsum, 2);
        if (qj == 0) ((float*)(sm + SM_L))[i] = lsum;
    }
    __syncthreads();

    // ---- epilogue: scale frags by 1/l and store ----
    const float* Ls = (const float*)(sm + SM_L);
#pragma unroll
    for (int mt = 0; mt < 2; ++mt) {
        int r0 = wy * 32 + mt * 16 + (lane >> 2);
        float inv0 = 1.f / Ls[r0];
        float inv1 = 1.f / Ls[r0 + 8];
        float* orow0 = out + ((size_t)(b * NN) + i0 + r0) * DD + wx * 32 + 2 * (lane & 3);
        float* orow1 = orow0 + 8 * DD;
#pragma unroll
        for (int nt = 0; nt < 4; ++nt) {
            float2 v0; v0.x = acc[mt][nt][0] * inv0; v0.y = acc[mt][nt][1] * inv0;
            float2 v1; v1.x = acc[mt][nt][2] * inv1; v1.y = acc[mt][nt][3] * inv1;
            *(float2*)(orow0 + nt * 8) = v0;
            *(float2*)(orow1 + nt * 8) = v1;
        }
    }
}

// ---------------------------------------------------------------------------
extern "C" void kernel_launch(void* const* d_in, const int* in_sizes, int n_in,
                              void* d_out, int out_size)
{
    const float* h     = (const float*)d_in[0];
    const int*   adj   = (const int*)d_in[1];
    const float* W     = (const float*)d_in[2];
    const float* a_src = (const float*)d_in[3];
    const float* a_dst = (const float*)d_in[4];
    float* out = (float*)d_out;

    cudaFuncSetAttribute(wh_gemm_kernel,  cudaFuncAttributeMaxDynamicSharedMemorySize, SMEM_A);
    cudaFuncSetAttribute(attn_mma_kernel, cudaFuncAttributeMaxDynamicSharedMemorySize, SMEM_B_TOTAL);

    wh_gemm_kernel<<<NB * NN / 64, 256, SMEM_A>>>(h, W, a_src, a_dst);
    attn_mma_kernel<<<dim3(NN / 128, NB), 512, SMEM_B_TOTAL>>>(adj, out);
}

// round 12
// speedup vs baseline: 1.1046x; 1.1046x over previous
#include <cuda_runtime.h>
#include <cuda_fp16.h>
#include <cstdint>
#include <math.h>

#define NB 8
#define NN 2048
#define DD 128
#define ALPHA 0.2f
#define PPAD 68

// ------------------------- device scratch ----------------------------------
__device__ __align__(16) unsigned short g_WhT_hi[NB * DD * NN];  // [b][d][j] fp16
__device__ __align__(16) float4 g_row4[NB * NN];  // (es, exp(es), exp(.2es), 0)
__device__ __align__(16) float4 g_col4[NB * NN];  // (ed, exp(ed), exp(.2ed), 0)

// ------------------------- helpers -----------------------------------------
__device__ __forceinline__ uint32_t smem_u32(const void* p) {
    uint32_t a;
    asm("{ .reg .u64 t; cvta.to.shared.u64 t, %1; cvt.u32.u64 %0, t; }" : "=r"(a) : "l"(p));
    return a;
}
#define SW128(o) ((o) ^ (((o) >> 3) & 0x70))

__device__ __forceinline__ void ldm_x4(uint32_t* r, uint32_t addr) {
    asm volatile("ldmatrix.sync.aligned.m8n8.x4.shared.b16 {%0,%1,%2,%3}, [%4];"
                 : "=r"(r[0]), "=r"(r[1]), "=r"(r[2]), "=r"(r[3]) : "r"(addr));
}
__device__ __forceinline__ void mma_f16(float* c, const uint32_t* a, const uint32_t* b) {
    asm volatile("mma.sync.aligned.m16n8k16.row.col.f32.f16.f16.f32 "
                 "{%0,%1,%2,%3}, {%4,%5,%6,%7}, {%8,%9}, {%0,%1,%2,%3};"
                 : "+f"(c[0]), "+f"(c[1]), "+f"(c[2]), "+f"(c[3])
                 : "r"(a[0]), "r"(a[1]), "r"(a[2]), "r"(a[3]), "r"(b[0]), "r"(b[1]));
}

#define CP_ASYNC16(dst, src) \
    asm volatile("cp.async.cg.shared.global [%0], [%1], 16;" :: "r"(dst), "l"(src) : "memory")
#define CP_COMMIT()  asm volatile("cp.async.commit_group;" ::: "memory")
#define CP_WAIT0()   asm volatile("cp.async.wait_group 0;" ::: "memory")

// ---- f32x2 helpers ---------------------------------------------------------
__device__ __forceinline__ void ffma2(unsigned long long& acc,
                                      unsigned long long a, unsigned long long b) {
    asm("fma.rn.f32x2 %0, %1, %2, %0;" : "+l"(acc) : "l"(a), "l"(b));
}
__device__ __forceinline__ unsigned long long pack2(float x, float y) {
    unsigned long long r;
    asm("mov.b64 %0, {%1, %2};" : "=l"(r) : "f"(x), "f"(y));
    return r;
}
__device__ __forceinline__ void unpack2(float& lo, float& hi, unsigned long long v) {
    asm("mov.b64 {%0, %1}, %2;" : "=f"(lo), "=f"(hi) : "l"(v));
}

// ---------------------------------------------------------------------------
// Kernel A: Wh = h @ W (FFMA2 GEMM, 64 rows/block), fused:
//   - fp16 Wh^T -> g_WhT_hi [b][d][j]
//   - g_row4/g_col4 factorized exp tables
// ---------------------------------------------------------------------------
#define SMEM_A (128*128*4 + 128*PPAD*4)

__global__ __launch_bounds__(256) void wh_gemm_kernel(
    const float* __restrict__ h, const float* __restrict__ W,
    const float* __restrict__ a_src, const float* __restrict__ a_dst)
{
    extern __shared__ __align__(16) char smem_raw[];
    float* Ws = (float*)smem_raw;               // [k][d] 128x128
    float* hs = Ws + 128 * 128;                 // [k][row] 128xPPAD

    int t = threadIdx.x;
    int r0blk = blockIdx.x * 64;

    {
        const float4* src = (const float4*)W;
        float4* dst = (float4*)Ws;
#pragma unroll
        for (int q = 0; q < 16; ++q) dst[t + q * 256] = src[t + q * 256];
    }
#pragma unroll
    for (int q = 0; q < 32; ++q) {
        int idx = t + q * 256;
        int k = idx & 127, row = idx >> 7;
        hs[k * PPAD + row] = h[(size_t)(r0blk + row) * DD + k];
    }
    __syncthreads();

    int tx = t & 15, ty = t >> 4;
    int d0 = tx * 8;

    unsigned long long acc[4][4];
#pragma unroll
    for (int r = 0; r < 4; ++r)
#pragma unroll
        for (int c = 0; c < 4; ++c) acc[r][c] = 0ull;

#pragma unroll 4
    for (int k = 0; k < 128; ++k) {
        float4 hv = *(const float4*)&hs[k * PPAD + ty * 4];
        ulonglong2 w0 = *(const ulonglong2*)&Ws[k * 128 + d0];
        ulonglong2 w1 = *(const ulonglong2*)&Ws[k * 128 + d0 + 4];
        unsigned long long pp[4];
        pp[0] = pack2(hv.x, hv.x); pp[1] = pack2(hv.y, hv.y);
        pp[2] = pack2(hv.z, hv.z); pp[3] = pack2(hv.w, hv.w);
#pragma unroll
        for (int r = 0; r < 4; ++r) {
            ffma2(acc[r][0], pp[r], w0.x);
            ffma2(acc[r][1], pp[r], w0.y);
            ffma2(acc[r][2], pp[r], w1.x);
            ffma2(acc[r][3], pp[r], w1.y);
        }
    }

    float asv[8], adv[8];
    {
        float4 s0 = *(const float4*)&a_src[d0];
        float4 s1 = *(const float4*)&a_src[d0 + 4];
        float4 t0 = *(const float4*)&a_dst[d0];
        float4 t1 = *(const float4*)&a_dst[d0 + 4];
        asv[0]=s0.x; asv[1]=s0.y; asv[2]=s0.z; asv[3]=s0.w;
        asv[4]=s1.x; asv[5]=s1.y; asv[6]=s1.z; asv[7]=s1.w;
        adv[0]=t0.x; adv[1]=t0.y; adv[2]=t0.z; adv[3]=t0.w;
        adv[4]=t1.x; adv[5]=t1.y; adv[6]=t1.z; adv[7]=t1.w;
    }

#pragma unroll
    for (int r = 0; r < 4; ++r) {
        int row = r0blk + ty * 4 + r;
        float w[8];
        unpack2(w[0], w[1], acc[r][0]); unpack2(w[2], w[3], acc[r][1]);
        unpack2(w[4], w[5], acc[r][2]); unpack2(w[6], w[7], acc[r][3]);
        float sa = 0.f, sd = 0.f;
#pragma unroll
        for (int c = 0; c < 8; ++c) { sa = fmaf(w[c], asv[c], sa); sd = fmaf(w[c], adv[c], sd); }
#pragma unroll
        for (int off = 8; off > 0; off >>= 1) {
            sa += __shfl_xor_sync(0xffffffffu, sa, off);
            sd += __shfl_xor_sync(0xffffffffu, sd, off);
        }
        if (tx == 0) {
            g_row4[row] = make_float4(sa, __expf(sa), __expf(ALPHA * sa), 0.f);
            g_col4[row] = make_float4(sd, __expf(sd), __expf(ALPHA * sd), 0.f);
        }
    }

    // ---- transpose + fp16 staging (reuse hs region) ----
    __syncthreads();
    unsigned short* sthi = (unsigned short*)hs;          // [128 d][64 j]
#pragma unroll
    for (int r = 0; r < 4; ++r) {
        float w[8];
        unpack2(w[0], w[1], acc[r][0]); unpack2(w[2], w[3], acc[r][1]);
        unpack2(w[4], w[5], acc[r][2]); unpack2(w[6], w[7], acc[r][3]);
        int jl = ty * 4 + r;
#pragma unroll
        for (int c = 0; c < 8; ++c)
            sthi[(d0 + c) * 64 + jl] = __half_as_ushort(__float2half_rn(w[c]));
    }
    __syncthreads();

    int b = r0blk >> 11;
    int jblk = r0blk & (NN - 1);
    const uint4* s4h = (const uint4*)sthi;
    uint4* gh = (uint4*)g_WhT_hi;
#pragma unroll
    for (int q = 0; q < 4; ++q) {
        int idx = t + 256 * q;
        int d = idx >> 3, ch = idx & 7;
        size_t dst = (size_t)(b * DD + d) * 256 + (jblk >> 3) + ch;
        gh[dst] = s4h[idx];
    }
}

// ---------------------------------------------------------------------------
// Kernel B: pipelined single-GEMM fp16 aggregation. Grid (32, 8), 256 thr,
//  2 blocks/SM. Block tile 64 i x 128 d; warp grid 2(i) x 4(d), warp tile
//  32 i x 32 d. P fp16 double-buffered (8KB ea); V fp16 double-buffered
//  (16KB ea, cp.async). out = P * V.
// ---------------------------------------------------------------------------
#define SM_COL4 0            // 32768 B
#define SM_P    32768        // + buf*8192
#define SM_V    49152        // + buf*16384
#define SM_L    81920        // 64 floats
#define SMEM_B_TOTAL 82176

__global__ __launch_bounds__(256, 2) void attn_mma_kernel(
    const int* __restrict__ adj, float* __restrict__ out)
{
    extern __shared__ __align__(1024) char sm[];
    uint32_t smb = smem_u32(sm);
    int t = threadIdx.x, wid = t >> 5, lane = t & 31;
    int b = blockIdx.y;
    int i0 = blockIdx.x * 64;
    int wy = wid & 1, wx = wid >> 1;

    // col factor table for this batch
    {
        const float4* src = g_col4 + b * NN;
        float4* dst = (float4*)(sm + SM_COL4);
#pragma unroll
        for (int q = 0; q < 8; ++q) dst[t + 256 * q] = src[t + 256 * q];
    }

    int i = t >> 2, qj = t & 3;        // fillP: row i (0..63), j-quarter (16 j)
    float4 rv = g_row4[b * NN + i0 + i];
    float esi = rv.x, Ai = rv.y, Ci = rv.z;
    const int* __restrict__ adjrow = adj + (size_t)(i0 + i) * NN;
    const float4* col4 = (const float4*)(sm + SM_COL4);
    const uint4* vhi_g = (const uint4*)g_WhT_hi + (size_t)b * DD * 256;
    float lsum = 0.f;

    __syncthreads();   // col4 ready

    float acc[2][4][4];
#pragma unroll
    for (int m = 0; m < 2; ++m)
#pragma unroll
        for (int n = 0; n < 4; ++n)
#pragma unroll
            for (int q = 0; q < 4; ++q) acc[m][n][q] = 0.f;

    int grp = lane >> 3, lrow = lane & 7;

    // ---- pipeline helpers ----
    auto loadV = [&](int c, int buf) {
        uint32_t vbase = smb + SM_V + buf * 16384;
        int j8 = (c * 64) >> 3;
#pragma unroll
        for (int q = 0; q < 4; ++q) {
            int idx = t + 256 * q;              // 0..1023
            int d = idx >> 3, ch = idx & 7;     // d 0..127
            uint32_t off = SW128((uint32_t)(d * 128 + ch * 16));
            CP_ASYNC16(vbase + off, (const char*)(vhi_g + d * 256 + j8 + ch));
        }
    };
    auto loadAdj = [&](int c, int4* am) {
        const int4* arow4 = (const int4*)(adjrow + c * 64 + qj * 16);
#pragma unroll
        for (int u = 0; u < 4; ++u) am[u] = __ldg(arow4 + u);
    };
    auto fillP = [&](int c, int buf, const int4* am) {
        int j0 = c * 64;
        char* ph_base = sm + SM_P + buf * 8192;
#pragma unroll
        for (int g = 0; g < 2; ++g) {           // 8 j per uint4 group
            uint32_t hw[4];
#pragma unroll
            for (int pr = 0; pr < 4; ++pr) {
                int jj = g * 8 + pr * 2;        // local 0..15
                int jg = j0 + qj * 16 + jj;
                int a0, a1;
                {
                    int4 av = am[jj >> 2];
                    if ((jj & 3) == 0) { a0 = av.x; a1 = av.y; }
                    else               { a0 = av.z; a1 = av.w; }
                }
                float4 c0 = col4[jg];
                float4 c1 = col4[jg + 1];
                float s0 = esi + c0.x;
                float s1 = esi + c1.x;
                float v0 = (s0 > 0.f) ? Ai * c0.y : Ci * c0.z;
                float v1 = (s1 > 0.f) ? Ai * c1.y : Ci * c1.z;
                float p0 = (a0 > 0) ? v0 : 0.f;
                float p1 = (a1 > 0) ? v1 : 0.f;
                lsum += p0 + p1;
                __half2 hh = __floats2half2_rn(p0, p1);   // p0 -> low half (j even)
                hw[pr] = *reinterpret_cast<uint32_t*>(&hh);
            }
            uint32_t off = SW128((uint32_t)(i * 128 + qj * 32 + g * 16));
            *(uint4*)(ph_base + off) = make_uint4(hw[0], hw[1], hw[2], hw[3]);
        }
    };

    // ---- prologue: fill buffer 0 ----
    int4 am[4];
    loadV(0, 0); CP_COMMIT();
    loadAdj(0, am);
    fillP(0, 0, am);
    CP_WAIT0();
    __syncthreads();

    // ---- main pipelined loop ----
    for (int c = 0; c < 32; ++c) {
        int cb = c & 1, nb = cb ^ 1;

        if (c < 31) {
            loadV(c + 1, nb); CP_COMMIT();
            loadAdj(c + 1, am);
        }

        // MMA on buffer cb
        {
            uint32_t phb = smb + SM_P + cb * 8192;
            uint32_t vhb = smb + SM_V + cb * 16384;
#pragma unroll
            for (int ks = 0; ks < 4; ++ks) {
                uint32_t ah[2][4];
#pragma unroll
                for (int mt = 0; mt < 2; ++mt) {
                    int arow = wy * 32 + mt * 16 + (grp & 1) * 8 + lrow;
                    uint32_t aoff = SW128((uint32_t)(arow * 128 + ks * 32 + (grp >> 1) * 16));
                    ldm_x4(ah[mt], phb + aoff);
                }
#pragma unroll
                for (int np = 0; np < 2; ++np) {
                    int brow = wx * 32 + np * 16 + (grp >> 1) * 8 + lrow;
                    uint32_t boff = SW128((uint32_t)(brow * 128 + ks * 32 + (grp & 1) * 16));
                    uint32_t bh[4];
                    ldm_x4(bh, vhb + boff);
#pragma unroll
                    for (int mt = 0; mt < 2; ++mt) {
                        mma_f16(acc[mt][np * 2],     ah[mt], bh);
                        mma_f16(acc[mt][np * 2 + 1], ah[mt], bh + 2);
                    }
                }
            }
        }

        if (c < 31) fillP(c + 1, nb, am);
        CP_WAIT0();
        __syncthreads();
    }

    // ---- row sums -> smem (4 threads per row) ----
    {
        lsum += __shfl_xor_sync(0xffffffffu, lsum, 1);
        lsum += __shfl_xor_sync(0xffffffffu, lsum, 2);
        if (qj == 0) ((float*)(sm + SM_L))[i] = lsum;
    }
    __syncthreads();

    // ---- epilogue: scale frags by 1/l and store ----
    const float* Ls = (const float*)(sm + SM_L);
#pragma unroll
    for (int mt = 0; mt < 2; ++mt) {
        int r0 = wy * 32 + mt * 16 + (lane >> 2);
        float inv0 = 1.f / Ls[r0];
        float inv1 = 1.f / Ls[r0 + 8];
        float* orow0 = out + ((size_t)(b * NN) + i0 + r0) * DD + wx * 32 + 2 * (lane & 3);
        float* orow1 = orow0 + 8 * DD;
#pragma unroll
        for (int nt = 0; nt < 4; ++nt) {
            float2 v0; v0.x = acc[mt][nt][0] * inv0; v0.y = acc[mt][nt][1] * inv0;
            float2 v1; v1.x = acc[mt][nt][2] * inv1; v1.y = acc[mt][nt][3] * inv1;
            *(float2*)(orow0 + nt * 8) = v0;
            *(float2*)(orow1 + nt * 8) = v1;
        }
    }
}

// ---------------------------------------------------------------------------
extern "C" void kernel_launch(void* const* d_in, const int* in_sizes, int n_in,
                              void* d_out, int out_size)
{
    const float* h     = (const float*)d_in[0];
    const int*   adj   = (const int*)d_in[1];
    const float* W     = (const float*)d_in[2];
    const float* a_src = (const float*)d_in[3];
    const float* a_dst = (const float*)d_in[4];
    float* out = (float*)d_out;

    cudaFuncSetAttribute(wh_gemm_kernel,  cudaFuncAttributeMaxDynamicSharedMemorySize, SMEM_A);
    cudaFuncSetAttribute(attn_mma_kernel, cudaFuncAttributeMaxDynamicSharedMemorySize, SMEM_B_TOTAL);

    wh_gemm_kernel<<<NB * NN / 64, 256, SMEM_A>>>(h, W, a_src, a_dst);
    attn_mma_kernel<<<dim3(NN / 64, NB), 256, SMEM_B_TOTAL>>>(adj, out);
}

// round 14
// speedup vs baseline: 1.5257x; 1.3812x over previous
#include <cuda_runtime.h>
#include <cuda_fp16.h>
#include <cstdint>
#include <math.h>

#define NB 8
#define NN 2048
#define DD 128
#define ALPHA 0.2f
#define PPAD 68

// ------------------------- device scratch ----------------------------------
__device__ __align__(16) unsigned short g_WhT_hi[NB * DD * NN];  // [b][d][j] fp16
__device__ __align__(16) float4 g_row4[NB * NN];  // (es, exp(es), exp(.2es), 0)
__device__ __align__(16) float4 g_col4[NB * NN];  // (ed, exp(ed), exp(.2ed), 0)

// ------------------------- helpers -----------------------------------------
__device__ __forceinline__ uint32_t smem_u32(const void* p) {
    uint32_t a;
    asm("{ .reg .u64 t; cvta.to.shared.u64 t, %1; cvt.u32.u64 %0, t; }" : "=r"(a) : "l"(p));
    return a;
}
#define SW128(o) ((o) ^ (((o) >> 3) & 0x70))

__device__ __forceinline__ void ldm_x4(uint32_t* r, uint32_t addr) {
    asm volatile("ldmatrix.sync.aligned.m8n8.x4.shared.b16 {%0,%1,%2,%3}, [%4];"
                 : "=r"(r[0]), "=r"(r[1]), "=r"(r[2]), "=r"(r[3]) : "r"(addr));
}
__device__ __forceinline__ void mma_f16(float* c, const uint32_t* a, const uint32_t* b) {
    asm volatile("mma.sync.aligned.m16n8k16.row.col.f32.f16.f16.f32 "
                 "{%0,%1,%2,%3}, {%4,%5,%6,%7}, {%8,%9}, {%0,%1,%2,%3};"
                 : "+f"(c[0]), "+f"(c[1]), "+f"(c[2]), "+f"(c[3])
                 : "r"(a[0]), "r"(a[1]), "r"(a[2]), "r"(a[3]), "r"(b[0]), "r"(b[1]));
}

#define CP_ASYNC16(dst, src) \
    asm volatile("cp.async.cg.shared.global [%0], [%1], 16;" :: "r"(dst), "l"(src) : "memory")
#define CP_COMMIT()  asm volatile("cp.async.commit_group;" ::: "memory")
#define CP_WAIT0()   asm volatile("cp.async.wait_group 0;" ::: "memory")

// named barriers (count 256): full0=1, full1=2, empty0=3, empty1=4, join=5
#define BAR_SYNC(id)   asm volatile("bar.sync %0, 256;"   :: "r"(id) : "memory")
#define BAR_ARRIVE(id) asm volatile("bar.arrive %0, 256;" :: "r"(id) : "memory")

// ---- f32x2 helpers ---------------------------------------------------------
__device__ __forceinline__ void ffma2(unsigned long long& acc,
                                      unsigned long long a, unsigned long long b) {
    asm("fma.rn.f32x2 %0, %1, %2, %0;" : "+l"(acc) : "l"(a), "l"(b));
}
__device__ __forceinline__ unsigned long long pack2(float x, float y) {
    unsigned long long r;
    asm("mov.b64 %0, {%1, %2};" : "=l"(r) : "f"(x), "f"(y));
    return r;
}
__device__ __forceinline__ void unpack2(float& lo, float& hi, unsigned long long v) {
    asm("mov.b64 {%0, %1}, %2;" : "=f"(lo), "=f"(hi) : "l"(v));
}

// ---------------------------------------------------------------------------
// Kernel A: Wh = h @ W (FFMA2 GEMM, 64 rows/block), fused:
//   - fp16 Wh^T -> g_WhT_hi [b][d][j]
//   - g_row4/g_col4 factorized exp tables
// ---------------------------------------------------------------------------
#define SMEM_A (128*128*4 + 128*PPAD*4)

__global__ __launch_bounds__(256) void wh_gemm_kernel(
    const float* __restrict__ h, const float* __restrict__ W,
    const float* __restrict__ a_src, const float* __restrict__ a_dst)
{
    extern __shared__ __align__(16) char smem_raw[];
    float* Ws = (float*)smem_raw;               // [k][d] 128x128
    float* hs = Ws + 128 * 128;                 // [k][row] 128xPPAD

    int t = threadIdx.x;
    int r0blk = blockIdx.x * 64;

    {
        const float4* src = (const float4*)W;
        float4* dst = (float4*)Ws;
#pragma unroll
        for (int q = 0; q < 16; ++q) dst[t + q * 256] = src[t + q * 256];
    }
#pragma unroll
    for (int q = 0; q < 32; ++q) {
        int idx = t + q * 256;
        int k = idx & 127, row = idx >> 7;
        hs[k * PPAD + row] = h[(size_t)(r0blk + row) * DD + k];
    }
    __syncthreads();

    int tx = t & 15, ty = t >> 4;
    int d0 = tx * 8;

    unsigned long long acc[4][4];
#pragma unroll
    for (int r = 0; r < 4; ++r)
#pragma unroll
        for (int c = 0; c < 4; ++c) acc[r][c] = 0ull;

#pragma unroll 4
    for (int k = 0; k < 128; ++k) {
        float4 hv = *(const float4*)&hs[k * PPAD + ty * 4];
        ulonglong2 w0 = *(const ulonglong2*)&Ws[k * 128 + d0];
        ulonglong2 w1 = *(const ulonglong2*)&Ws[k * 128 + d0 + 4];
        unsigned long long pp[4];
        pp[0] = pack2(hv.x, hv.x); pp[1] = pack2(hv.y, hv.y);
        pp[2] = pack2(hv.z, hv.z); pp[3] = pack2(hv.w, hv.w);
#pragma unroll
        for (int r = 0; r < 4; ++r) {
            ffma2(acc[r][0], pp[r], w0.x);
            ffma2(acc[r][1], pp[r], w0.y);
            ffma2(acc[r][2], pp[r], w1.x);
            ffma2(acc[r][3], pp[r], w1.y);
        }
    }

    float asv[8], adv[8];
    {
        float4 s0 = *(const float4*)&a_src[d0];
        float4 s1 = *(const float4*)&a_src[d0 + 4];
        float4 t0 = *(const float4*)&a_dst[d0];
        float4 t1 = *(const float4*)&a_dst[d0 + 4];
        asv[0]=s0.x; asv[1]=s0.y; asv[2]=s0.z; asv[3]=s0.w;
        asv[4]=s1.x; asv[5]=s1.y; asv[6]=s1.z; asv[7]=s1.w;
        adv[0]=t0.x; adv[1]=t0.y; adv[2]=t0.z; adv[3]=t0.w;
        adv[4]=t1.x; adv[5]=t1.y; adv[6]=t1.z; adv[7]=t1.w;
    }

#pragma unroll
    for (int r = 0; r < 4; ++r) {
        int row = r0blk + ty * 4 + r;
        float w[8];
        unpack2(w[0], w[1], acc[r][0]); unpack2(w[2], w[3], acc[r][1]);
        unpack2(w[4], w[5], acc[r][2]); unpack2(w[6], w[7], acc[r][3]);
        float sa = 0.f, sd = 0.f;
#pragma unroll
        for (int c = 0; c < 8; ++c) { sa = fmaf(w[c], asv[c], sa); sd = fmaf(w[c], adv[c], sd); }
#pragma unroll
        for (int off = 8; off > 0; off >>= 1) {
            sa += __shfl_xor_sync(0xffffffffu, sa, off);
            sd += __shfl_xor_sync(0xffffffffu, sd, off);
        }
        if (tx == 0) {
            g_row4[row] = make_float4(sa, __expf(sa), __expf(ALPHA * sa), 0.f);
            g_col4[row] = make_float4(sd, __expf(sd), __expf(ALPHA * sd), 0.f);
        }
    }

    // ---- transpose + fp16 staging (reuse hs region) ----
    __syncthreads();
    unsigned short* sthi = (unsigned short*)hs;          // [128 d][64 j]
#pragma unroll
    for (int r = 0; r < 4; ++r) {
        float w[8];
        unpack2(w[0], w[1], acc[r][0]); unpack2(w[2], w[3], acc[r][1]);
        unpack2(w[4], w[5], acc[r][2]); unpack2(w[6], w[7], acc[r][3]);
        int jl = ty * 4 + r;
#pragma unroll
        for (int c = 0; c < 8; ++c)
            sthi[(d0 + c) * 64 + jl] = __half_as_ushort(__float2half_rn(w[c]));
    }
    __syncthreads();

    int b = r0blk >> 11;
    int jblk = r0blk & (NN - 1);
    const uint4* s4h = (const uint4*)sthi;
    uint4* gh = (uint4*)g_WhT_hi;
#pragma unroll
    for (int q = 0; q < 4; ++q) {
        int idx = t + 256 * q;
        int d = idx >> 3, ch = idx & 7;
        size_t dst = (size_t)(b * DD + d) * 256 + (jblk >> 3) + ch;
        gh[dst] = s4h[idx];
    }
}

// ---------------------------------------------------------------------------
// Kernel B: warp-specialized fp16 HMMA aggregation. Grid (16, 8), 256 thr.
//  Block tile 128 i x 128 d. Warps 0-3 = producers (P fill, 1 thread/row;
//  V cp.async). Warps 4-7 = consumers (warp tile 64i x 64d, pure LDSM+MMA).
//  Double-buffered P (16KB ea) and V (16KB ea); named-barrier ping-pong.
// ---------------------------------------------------------------------------
#define SM_COL4 0            // 32768 B
#define SM_P    32768        // + buf*16384
#define SM_V    65536        // + buf*16384
#define SM_L    98304        // 128 floats
#define SMEM_B_TOTAL 98816

__global__ __launch_bounds__(256, 1) void attn_mma_kernel(
    const int* __restrict__ adj, float* __restrict__ out)
{
    extern __shared__ __align__(1024) char sm[];
    uint32_t smb = smem_u32(sm);
    int t = threadIdx.x, wid = t >> 5, lane = t & 31;
    int b = blockIdx.y;
    int i0 = blockIdx.x * 128;

    // col factor table for this batch (all 256 threads)
    {
        const float4* src = g_col4 + b * NN;
        float4* dst = (float4*)(sm + SM_COL4);
#pragma unroll
        for (int q = 0; q < 8; ++q) dst[t + 256 * q] = src[t + 256 * q];
    }
    __syncthreads();

    if (wid < 4) {
        // ======================= PRODUCER (threads 0..127) ==================
        int i = t;                                  // one thread per i-row
        float4 rv = g_row4[b * NN + i0 + i];
        float esi = rv.x, Ai = rv.y, Ci = rv.z;
        const int* __restrict__ adjrow = adj + (size_t)(i0 + i) * NN;
        const float4* col4s = (const float4*)(sm + SM_COL4);
        const uint4* vhi_g = (const uint4*)g_WhT_hi + (size_t)b * DD * 256;
        float lsum = 0.f;

        for (int c = 0; c < 32; ++c) {
            int buf = c & 1;
            if (c >= 2) BAR_SYNC(3 + buf);          // wait buffer empty

            // V tile cp.async: 1024 uint4 chunks over 128 threads
            {
                uint32_t vbase = smb + SM_V + buf * 16384;
                int j8 = c * 8;
#pragma unroll
                for (int q = 0; q < 8; ++q) {
                    int idx = t + 128 * q;
                    int d = idx >> 3, ch = idx & 7;
                    uint32_t off = SW128((uint32_t)(d * 128 + ch * 16));
                    CP_ASYNC16(vbase + off, (const char*)(vhi_g + d * 256 + j8 + ch));
                }
                CP_COMMIT();
            }

            // adj for this row: full 64 j = 16 int4
            int4 am[16];
            {
                const int4* a4 = (const int4*)(adjrow + c * 64);
#pragma unroll
                for (int u = 0; u < 16; ++u) am[u] = __ldg(a4 + u);
            }
            const int* ai = (const int*)am;

            // P row fill: row i, 64 j -> 8 uint4 stores
            {
                char* ph = sm + SM_P + buf * 16384;
                int jb = c * 64;
#pragma unroll
                for (int g = 0; g < 8; ++g) {
                    uint32_t hw[4];
#pragma unroll
                    for (int pr = 0; pr < 4; ++pr) {
                        int jj = g * 8 + pr * 2;
                        int a0 = ai[jj], a1 = ai[jj + 1];
                        float4 c0 = col4s[jb + jj];
                        float4 c1 = col4s[jb + jj + 1];
                        float s0 = esi + c0.x;
                        float s1 = esi + c1.x;
                        float v0 = (s0 > 0.f) ? Ai * c0.y : Ci * c0.z;
                        float v1 = (s1 > 0.f) ? Ai * c1.y : Ci * c1.z;
                        float p0 = (a0 > 0) ? v0 : 0.f;
                        float p1 = (a1 > 0) ? v1 : 0.f;
                        lsum += p0 + p1;
                        __half2 hh = __floats2half2_rn(p0, p1);
                        hw[pr] = *reinterpret_cast<uint32_t*>(&hh);
                    }
                    uint32_t off = SW128((uint32_t)(i * 128 + g * 16));
                    *(uint4*)(ph + off) = make_uint4(hw[0], hw[1], hw[2], hw[3]);
                }
            }

            CP_WAIT0();
            BAR_ARRIVE(1 + buf);                    // signal buffer full
        }
        ((float*)(sm + SM_L))[i] = lsum;
        BAR_ARRIVE(5);                              // join: L ready
    } else {
        // ======================= CONSUMER (threads 128..255) ================
        int cwid = wid - 4;
        int wy = cwid & 1, wx = cwid >> 1;          // 2(i) x 2(d), tile 64i x 64d
        int grp = lane >> 3, lrow = lane & 7;

        float acc[4][8][4];
#pragma unroll
        for (int m = 0; m < 4; ++m)
#pragma unroll
            for (int n = 0; n < 8; ++n)
#pragma unroll
                for (int q = 0; q < 4; ++q) acc[m][n][q] = 0.f;

        for (int c = 0; c < 32; ++c) {
            int buf = c & 1;
            BAR_SYNC(1 + buf);                      // wait buffer full
            uint32_t phb = smb + SM_P + buf * 16384;
            uint32_t vhb = smb + SM_V + buf * 16384;
#pragma unroll
            for (int ks = 0; ks < 4; ++ks) {
                uint32_t ah[4][4];
#pragma unroll
                for (int mt = 0; mt < 4; ++mt) {
                    int arow = wy * 64 + mt * 16 + (grp & 1) * 8 + lrow;
                    uint32_t aoff = SW128((uint32_t)(arow * 128 + ks * 32 + (grp >> 1) * 16));
                    ldm_x4(ah[mt], phb + aoff);
                }
#pragma unroll
                for (int np = 0; np < 4; ++np) {
                    int brow = wx * 64 + np * 16 + (grp >> 1) * 8 + lrow;
                    uint32_t boff = SW128((uint32_t)(brow * 128 + ks * 32 + (grp & 1) * 16));
                    uint32_t bh[4];
                    ldm_x4(bh, vhb + boff);
#pragma unroll
                    for (int mt = 0; mt < 4; ++mt) {
                        mma_f16(acc[mt][np * 2],     ah[mt], bh);
                        mma_f16(acc[mt][np * 2 + 1], ah[mt], bh + 2);
                    }
                }
            }
            BAR_ARRIVE(3 + buf);                    // signal buffer empty
        }
        BAR_SYNC(5);                                // join: wait for L

        // epilogue: scale by 1/l and store
        const float* Ls = (const float*)(sm + SM_L);
#pragma unroll
        for (int mt = 0; mt < 4; ++mt) {
            int r0 = wy * 64 + mt * 16 + (lane >> 2);
            float inv0 = 1.f / Ls[r0];
            float inv1 = 1.f / Ls[r0 + 8];
            float* orow0 = out + ((size_t)(b * NN) + i0 + r0) * DD + wx * 64 + 2 * (lane & 3);
            float* orow1 = orow0 + 8 * DD;
#pragma unroll
            for (int nt = 0; nt < 8; ++nt) {
                float2 v0; v0.x = acc[mt][nt][0] * inv0; v0.y = acc[mt][nt][1] * inv0;
                float2 v1; v1.x = acc[mt][nt][2] * inv1; v1.y = acc[mt][nt][3] * inv1;
                *(float2*)(orow0 + nt * 8) = v0;
                *(float2*)(orow1 + nt * 8) = v1;
            }
        }
    }
}

// ---------------------------------------------------------------------------
extern "C" void kernel_launch(void* const* d_in, const int* in_sizes, int n_in,
                              void* d_out, int out_size)
{
    const float* h     = (const float*)d_in[0];
    const int*   adj   = (const int*)d_in[1];
    const float* W     = (const float*)d_in[2];
    const float* a_src = (const float*)d_in[3];
    const float* a_dst = (const float*)d_in[4];
    float* out = (float*)d_out;

    cudaFuncSetAttribute(wh_gemm_kernel,  cudaFuncAttributeMaxDynamicSharedMemorySize, SMEM_A);
    cudaFuncSetAttribute(attn_mma_kernel, cudaFuncAttributeMaxDynamicSharedMemorySize, SMEM_B_TOTAL);

    wh_gemm_kernel<<<NB * NN / 64, 256, SMEM_A>>>(h, W, a_src, a_dst);
    attn_mma_kernel<<<dim3(NN / 128, NB), 256, SMEM_B_TOTAL>>>(adj, out);
}

// round 16
// speedup vs baseline: 1.6267x; 1.0662x over previous
#include <cuda_runtime.h>
#include <cuda_fp16.h>
#include <cstdint>
#include <math.h>

#define NB 8
#define NN 2048
#define DD 128
#define ALPHA 0.2f
#define PPAD 68

// ------------------------- device scratch ----------------------------------
__device__ __align__(16) unsigned short g_WhT_hi[NB * DD * NN];  // [b][d][j] fp16
__device__ __align__(16) float4 g_row4[NB * NN];  // (es, exp(es), exp(.2es), 0)
__device__ __align__(16) float4 g_col4[NB * NN];  // (ed, exp(ed), exp(.2ed), 0)

// ------------------------- helpers -----------------------------------------
__device__ __forceinline__ uint32_t smem_u32(const void* p) {
    uint32_t a;
    asm("{ .reg .u64 t; cvta.to.shared.u64 t, %1; cvt.u32.u64 %0, t; }" : "=r"(a) : "l"(p));
    return a;
}
#define SW128(o) ((o) ^ (((o) >> 3) & 0x70))

__device__ __forceinline__ void ldm_x4(uint32_t* r, uint32_t addr) {
    asm volatile("ldmatrix.sync.aligned.m8n8.x4.shared.b16 {%0,%1,%2,%3}, [%4];"
                 : "=r"(r[0]), "=r"(r[1]), "=r"(r[2]), "=r"(r[3]) : "r"(addr));
}
__device__ __forceinline__ void mma_f16(float* c, const uint32_t* a, const uint32_t* b) {
    asm volatile("mma.sync.aligned.m16n8k16.row.col.f32.f16.f16.f32 "
                 "{%0,%1,%2,%3}, {%4,%5,%6,%7}, {%8,%9}, {%0,%1,%2,%3};"
                 : "+f"(c[0]), "+f"(c[1]), "+f"(c[2]), "+f"(c[3])
                 : "r"(a[0]), "r"(a[1]), "r"(a[2]), "r"(a[3]), "r"(b[0]), "r"(b[1]));
}

#define CP_ASYNC16(dst, src) \
    asm volatile("cp.async.cg.shared.global [%0], [%1], 16;" :: "r"(dst), "l"(src) : "memory")
#define CP_COMMIT()  asm volatile("cp.async.commit_group;" ::: "memory")
#define CP_WAIT0()   asm volatile("cp.async.wait_group 0;" ::: "memory")

// named barriers (count 384): full(s)=1+s, empty(s)=4+s (s=0..2), join=7
#define BAR_SYNC(id)   asm volatile("bar.sync %0, 384;"   :: "r"(id) : "memory")
#define BAR_ARRIVE(id) asm volatile("bar.arrive %0, 384;" :: "r"(id) : "memory")

// ---- f32x2 helpers ---------------------------------------------------------
__device__ __forceinline__ void ffma2(unsigned long long& acc,
                                      unsigned long long a, unsigned long long b) {
    asm("fma.rn.f32x2 %0, %1, %2, %0;" : "+l"(acc) : "l"(a), "l"(b));
}
__device__ __forceinline__ unsigned long long pack2(float x, float y) {
    unsigned long long r;
    asm("mov.b64 %0, {%1, %2};" : "=l"(r) : "f"(x), "f"(y));
    return r;
}
__device__ __forceinline__ void unpack2(float& lo, float& hi, unsigned long long v) {
    asm("mov.b64 {%0, %1}, %2;" : "=f"(lo), "=f"(hi) : "l"(v));
}

// ---------------------------------------------------------------------------
// Kernel A: Wh = h @ W (FFMA2 GEMM, 64 rows/block), fused:
//   - fp16 Wh^T -> g_WhT_hi [b][d][j]
//   - g_row4/g_col4 factorized exp tables
// ---------------------------------------------------------------------------
#define SMEM_A (128*128*4 + 128*PPAD*4)

__global__ __launch_bounds__(256) void wh_gemm_kernel(
    const float* __restrict__ h, const float* __restrict__ W,
    const float* __restrict__ a_src, const float* __restrict__ a_dst)
{
    extern __shared__ __align__(16) char smem_raw[];
    float* Ws = (float*)smem_raw;               // [k][d] 128x128
    float* hs = Ws + 128 * 128;                 // [k][row] 128xPPAD

    int t = threadIdx.x;
    int r0blk = blockIdx.x * 64;

    {
        const float4* src = (const float4*)W;
        float4* dst = (float4*)Ws;
#pragma unroll
        for (int q = 0; q < 16; ++q) dst[t + q * 256] = src[t + q * 256];
    }
#pragma unroll
    for (int q = 0; q < 32; ++q) {
        int idx = t + q * 256;
        int k = idx & 127, row = idx >> 7;
        hs[k * PPAD + row] = h[(size_t)(r0blk + row) * DD + k];
    }
    __syncthreads();

    int tx = t & 15, ty = t >> 4;
    int d0 = tx * 8;

    unsigned long long acc[4][4];
#pragma unroll
    for (int r = 0; r < 4; ++r)
#pragma unroll
        for (int c = 0; c < 4; ++c) acc[r][c] = 0ull;

#pragma unroll 4
    for (int k = 0; k < 128; ++k) {
        float4 hv = *(const float4*)&hs[k * PPAD + ty * 4];
        ulonglong2 w0 = *(const ulonglong2*)&Ws[k * 128 + d0];
        ulonglong2 w1 = *(const ulonglong2*)&Ws[k * 128 + d0 + 4];
        unsigned long long pp[4];
        pp[0] = pack2(hv.x, hv.x); pp[1] = pack2(hv.y, hv.y);
        pp[2] = pack2(hv.z, hv.z); pp[3] = pack2(hv.w, hv.w);
#pragma unroll
        for (int r = 0; r < 4; ++r) {
            ffma2(acc[r][0], pp[r], w0.x);
            ffma2(acc[r][1], pp[r], w0.y);
            ffma2(acc[r][2], pp[r], w1.x);
            ffma2(acc[r][3], pp[r], w1.y);
        }
    }

    float asv[8], adv[8];
    {
        float4 s0 = *(const float4*)&a_src[d0];
        float4 s1 = *(const float4*)&a_src[d0 + 4];
        float4 t0 = *(const float4*)&a_dst[d0];
        float4 t1 = *(const float4*)&a_dst[d0 + 4];
        asv[0]=s0.x; asv[1]=s0.y; asv[2]=s0.z; asv[3]=s0.w;
        asv[4]=s1.x; asv[5]=s1.y; asv[6]=s1.z; asv[7]=s1.w;
        adv[0]=t0.x; adv[1]=t0.y; adv[2]=t0.z; adv[3]=t0.w;
        adv[4]=t1.x; adv[5]=t1.y; adv[6]=t1.z; adv[7]=t1.w;
    }

#pragma unroll
    for (int r = 0; r < 4; ++r) {
        int row = r0blk + ty * 4 + r;
        float w[8];
        unpack2(w[0], w[1], acc[r][0]); unpack2(w[2], w[3], acc[r][1]);
        unpack2(w[4], w[5], acc[r][2]); unpack2(w[6], w[7], acc[r][3]);
        float sa = 0.f, sd = 0.f;
#pragma unroll
        for (int c = 0; c < 8; ++c) { sa = fmaf(w[c], asv[c], sa); sd = fmaf(w[c], adv[c], sd); }
#pragma unroll
        for (int off = 8; off > 0; off >>= 1) {
            sa += __shfl_xor_sync(0xffffffffu, sa, off);
            sd += __shfl_xor_sync(0xffffffffu, sd, off);
        }
        if (tx == 0) {
            g_row4[row] = make_float4(sa, __expf(sa), __expf(ALPHA * sa), 0.f);
            g_col4[row] = make_float4(sd, __expf(sd), __expf(ALPHA * sd), 0.f);
        }
    }

    // ---- transpose + fp16 staging (reuse hs region) ----
    __syncthreads();
    unsigned short* sthi = (unsigned short*)hs;          // [128 d][64 j]
#pragma unroll
    for (int r = 0; r < 4; ++r) {
        float w[8];
        unpack2(w[0], w[1], acc[r][0]); unpack2(w[2], w[3], acc[r][1]);
        unpack2(w[4], w[5], acc[r][2]); unpack2(w[6], w[7], acc[r][3]);
        int jl = ty * 4 + r;
#pragma unroll
        for (int c = 0; c < 8; ++c)
            sthi[(d0 + c) * 64 + jl] = __half_as_ushort(__float2half_rn(w[c]));
    }
    __syncthreads();

    int b = r0blk >> 11;
    int jblk = r0blk & (NN - 1);
    const uint4* s4h = (const uint4*)sthi;
    uint4* gh = (uint4*)g_WhT_hi;
#pragma unroll
    for (int q = 0; q < 4; ++q) {
        int idx = t + 256 * q;
        int d = idx >> 3, ch = idx & 7;
        size_t dst = (size_t)(b * DD + d) * 256 + (jblk >> 3) + ch;
        gh[dst] = s4h[idx];
    }
}

// ---------------------------------------------------------------------------
// Kernel B: warp-specialized fp16 HMMA aggregation. Grid (16, 8), 384 thr.
//  Block tile 128 i x 128 d. Warps 0-3 = producers (P fill 1 thread/row,
//  V cp.async). Warps 4-11 = consumers (2i x 4d grid, warp tile 64i x 32d).
//  3-stage pipeline for P (16KB ea) and V (16KB ea); named barriers.
// ---------------------------------------------------------------------------
#define SM_COL4 0            // 32768 B
#define SM_P    32768        // + buf*16384 (3 stages)
#define SM_V    81920        // + buf*16384 (3 stages)
#define SM_L    131072       // 128 floats
#define SMEM_B_TOTAL 131584

__global__ __launch_bounds__(384, 1) void attn_mma_kernel(
    const int* __restrict__ adj, float* __restrict__ out)
{
    extern __shared__ __align__(1024) char sm[];
    uint32_t smb = smem_u32(sm);
    int t = threadIdx.x, wid = t >> 5, lane = t & 31;
    int b = blockIdx.y;
    int i0 = blockIdx.x * 128;

    // col factor table for this batch (all 384 threads)
    {
        const float4* src = g_col4 + b * NN;
        float4* dst = (float4*)(sm + SM_COL4);
        for (int idx = t; idx < 2048; idx += 384) dst[idx] = src[idx];
    }
    __syncthreads();

    if (wid < 4) {
        // ======================= PRODUCER (threads 0..127) ==================
        int i = t;                                  // one thread per i-row
        float4 rv = g_row4[b * NN + i0 + i];
        float esi = rv.x, Ai = rv.y, Ci = rv.z;
        const int* __restrict__ adjrow = adj + (size_t)(i0 + i) * NN;
        const float4* col4s = (const float4*)(sm + SM_COL4);
        const uint4* vhi_g = (const uint4*)g_WhT_hi + (size_t)b * DD * 256;
        float lsum = 0.f;

        for (int c = 0; c < 32; ++c) {
            int buf = c - (c / 3) * 3;              // c % 3
            if (c >= 3) BAR_SYNC(4 + buf);          // wait stage empty

            // V tile cp.async: 1024 uint4 chunks over 128 threads
            {
                uint32_t vbase = smb + SM_V + buf * 16384;
                int j8 = c * 8;
#pragma unroll
                for (int q = 0; q < 8; ++q) {
                    int idx = t + 128 * q;
                    int d = idx >> 3, ch = idx & 7;
                    uint32_t off = SW128((uint32_t)(d * 128 + ch * 16));
                    CP_ASYNC16(vbase + off, (const char*)(vhi_g + d * 256 + j8 + ch));
                }
                CP_COMMIT();
            }

            // P row fill: 2 halves of 32 j (adj in 8 int4 regs per half)
            char* ph = sm + SM_P + buf * 16384;
            int jb = c * 64;
#pragma unroll
            for (int hh = 0; hh < 2; ++hh) {
                int4 am[8];
                const int4* a4 = (const int4*)(adjrow + jb + hh * 32);
#pragma unroll
                for (int u = 0; u < 8; ++u) am[u] = __ldg(a4 + u);
                const int* ai = (const int*)am;
#pragma unroll
                for (int g = 0; g < 4; ++g) {
                    uint32_t hw[4];
#pragma unroll
                    for (int pr = 0; pr < 4; ++pr) {
                        int jj = g * 8 + pr * 2;            // 0..31 within half
                        int jg = jb + hh * 32 + jj;
                        int a0 = ai[jj], a1 = ai[jj + 1];
                        float4 c0 = col4s[jg];
                        float4 c1 = col4s[jg + 1];
                        float s0 = esi + c0.x;
                        float s1 = esi + c1.x;
                        float v0 = (s0 > 0.f) ? Ai * c0.y : Ci * c0.z;
                        float v1 = (s1 > 0.f) ? Ai * c1.y : Ci * c1.z;
                        float p0 = (a0 > 0) ? v0 : 0.f;
                        float p1 = (a1 > 0) ? v1 : 0.f;
                        lsum += p0 + p1;
                        __half2 hhp = __floats2half2_rn(p0, p1);
                        hw[pr] = *reinterpret_cast<uint32_t*>(&hhp);
                    }
                    uint32_t off = SW128((uint32_t)(i * 128 + hh * 64 + g * 16));
                    *(uint4*)(ph + off) = make_uint4(hw[0], hw[1], hw[2], hw[3]);
                }
            }

            CP_WAIT0();
            BAR_ARRIVE(1 + buf);                    // signal stage full
        }
        ((float*)(sm + SM_L))[i] = lsum;
        BAR_ARRIVE(7);                              // join: L ready
    } else {
        // ======================= CONSUMER (threads 128..383) ================
        int cwid = wid - 4;                         // 0..7
        int wy = cwid & 1, wx = cwid >> 1;          // 2(i) x 4(d), tile 64i x 32d
        int grp = lane >> 3, lrow = lane & 7;

        float acc[4][4][4];
#pragma unroll
        for (int m = 0; m < 4; ++m)
#pragma unroll
            for (int n = 0; n < 4; ++n)
#pragma unroll
                for (int q = 0; q < 4; ++q) acc[m][n][q] = 0.f;

        for (int c = 0; c < 32; ++c) {
            int buf = c - (c / 3) * 3;              // c % 3
            BAR_SYNC(1 + buf);                      // wait stage full
            uint32_t phb = smb + SM_P + buf * 16384;
            uint32_t vhb = smb + SM_V + buf * 16384;
#pragma unroll
            for (int ks = 0; ks < 4; ++ks) {
                uint32_t ah[4][4];
#pragma unroll
                for (int mt = 0; mt < 4; ++mt) {
                    int arow = wy * 64 + mt * 16 + (grp & 1) * 8 + lrow;
                    uint32_t aoff = SW128((uint32_t)(arow * 128 + ks * 32 + (grp >> 1) * 16));
                    ldm_x4(ah[mt], phb + aoff);
                }
#pragma unroll
                for (int np = 0; np < 2; ++np) {
                    int brow = wx * 32 + np * 16 + (grp >> 1) * 8 + lrow;
                    uint32_t boff = SW128((uint32_t)(brow * 128 + ks * 32 + (grp & 1) * 16));
                    uint32_t bh[4];
                    ldm_x4(bh, vhb + boff);
#pragma unroll
                    for (int mt = 0; mt < 4; ++mt) {
                        mma_f16(acc[mt][np * 2],     ah[mt], bh);
                        mma_f16(acc[mt][np * 2 + 1], ah[mt], bh + 2);
                    }
                }
            }
            BAR_ARRIVE(4 + buf);                    // signal stage empty
        }
        BAR_SYNC(7);                                // join: wait for L

        // epilogue: scale by 1/l and store
        const float* Ls = (const float*)(sm + SM_L);
#pragma unroll
        for (int mt = 0; mt < 4; ++mt) {
            int r0 = wy * 64 + mt * 16 + (lane >> 2);
            float inv0 = 1.f / Ls[r0];
            float inv1 = 1.f / Ls[r0 + 8];
            float* orow0 = out + ((size_t)(b * NN) + i0 + r0) * DD + wx * 32 + 2 * (lane & 3);
            float* orow1 = orow0 + 8 * DD;
#pragma unroll
            for (int nt = 0; nt < 4; ++nt) {
                float2 v0; v0.x = acc[mt][nt][0] * inv0; v0.y = acc[mt][nt][1] * inv0;
                float2 v1; v1.x = acc[mt][nt][2] * inv1; v1.y = acc[mt][nt][3] * inv1;
                *(float2*)(orow0 + nt * 8) = v0;
                *(float2*)(orow1 + nt * 8) = v1;
            }
        }
    }
}

// ---------------------------------------------------------------------------
extern "C" void kernel_launch(void* const* d_in, const int* in_sizes, int n_in,
                              void* d_out, int out_size)
{
    const float* h     = (const float*)d_in[0];
    const int*   adj   = (const int*)d_in[1];
    const float* W     = (const float*)d_in[2];
    const float* a_src = (const float*)d_in[3];
    const float* a_dst = (const float*)d_in[4];
    float* out = (float*)d_out;

    cudaFuncSetAttribute(wh_gemm_kernel,  cudaFuncAttributeMaxDynamicSharedMemorySize, SMEM_A);
    cudaFuncSetAttribute(attn_mma_kernel, cudaFuncAttributeMaxDynamicSharedMemorySize, SMEM_B_TOTAL);

    wh_gemm_kernel<<<NB * NN / 64, 256, SMEM_A>>>(h, W, a_src, a_dst);
    attn_mma_kernel<<<dim3(NN / 128, NB), 384, SMEM_B_TOTAL>>>(adj, out);
}

// round 17
// speedup vs baseline: 2.0503x; 1.2604x over previous
#include <cuda_runtime.h>
#include <cuda_fp16.h>
#include <cstdint>
#include <math.h>

#define NB 8
#define NN 2048
#define DD 128
#define ALPHA 0.2f
#define PPAD 68

// ------------------------- device scratch ----------------------------------
__device__ __align__(16) unsigned short g_WhT_hi[NB * DD * NN];  // [b][d][j] fp16
__device__ __align__(16) float4 g_row4[NB * NN];  // (es, exp(es), exp(.2es), 0)
__device__ __align__(16) float4 g_col4[NB * NN];  // (ed, exp(ed), exp(.2ed), 0)
__device__ __align__(8)  uint2  g_adjbits[NN * 32];  // [i][c] 64-bit mask for j-tile c

// ------------------------- helpers -----------------------------------------
__device__ __forceinline__ uint32_t smem_u32(const void* p) {
    uint32_t a;
    asm("{ .reg .u64 t; cvta.to.shared.u64 t, %1; cvt.u32.u64 %0, t; }" : "=r"(a) : "l"(p));
    return a;
}
#define SW128(o) ((o) ^ (((o) >> 3) & 0x70))

__device__ __forceinline__ void ldm_x4(uint32_t* r, uint32_t addr) {
    asm volatile("ldmatrix.sync.aligned.m8n8.x4.shared.b16 {%0,%1,%2,%3}, [%4];"
                 : "=r"(r[0]), "=r"(r[1]), "=r"(r[2]), "=r"(r[3]) : "r"(addr));
}
__device__ __forceinline__ void mma_f16(float* c, const uint32_t* a, const uint32_t* b) {
    asm volatile("mma.sync.aligned.m16n8k16.row.col.f32.f16.f16.f32 "
                 "{%0,%1,%2,%3}, {%4,%5,%6,%7}, {%8,%9}, {%0,%1,%2,%3};"
                 : "+f"(c[0]), "+f"(c[1]), "+f"(c[2]), "+f"(c[3])
                 : "r"(a[0]), "r"(a[1]), "r"(a[2]), "r"(a[3]), "r"(b[0]), "r"(b[1]));
}

#define CP_ASYNC16(dst, src) \
    asm volatile("cp.async.cg.shared.global [%0], [%1], 16;" :: "r"(dst), "l"(src) : "memory")
#define CP_COMMIT()  asm volatile("cp.async.commit_group;" ::: "memory")
#define CP_WAITG(n)  asm volatile("cp.async.wait_group %0;" :: "n"(n) : "memory")

// named barriers (count 384): full(s)=1+s, empty(s)=4+s (s=0..2), join=7
#define BAR_SYNC(id)   asm volatile("bar.sync %0, 384;"   :: "r"(id) : "memory")
#define BAR_ARRIVE(id) asm volatile("bar.arrive %0, 384;" :: "r"(id) : "memory")

// ---- f32x2 helpers ---------------------------------------------------------
__device__ __forceinline__ void ffma2(unsigned long long& acc,
                                      unsigned long long a, unsigned long long b) {
    asm("fma.rn.f32x2 %0, %1, %2, %0;" : "+l"(acc) : "l"(a), "l"(b));
}
__device__ __forceinline__ unsigned long long pack2(float x, float y) {
    unsigned long long r;
    asm("mov.b64 %0, {%1, %2};" : "=l"(r) : "f"(x), "f"(y));
    return r;
}
__device__ __forceinline__ void unpack2(float& lo, float& hi, unsigned long long v) {
    asm("mov.b64 {%0, %1}, %2;" : "=f"(lo), "=f"(hi) : "l"(v));
}

// ---------------------------------------------------------------------------
// Kernel P: pack adjacency into 64-bit masks. Warp per (row, j-tile).
// ---------------------------------------------------------------------------
__global__ __launch_bounds__(256) void pack_adj_kernel(const int* __restrict__ adj)
{
    int gw = blockIdx.x * 8 + (threadIdx.x >> 5);   // 0 .. 65535
    int lane = threadIdx.x & 31;
    int row = gw >> 5, c = gw & 31;
    const int* p = adj + (size_t)row * NN + c * 64;
    uint32_t lo = __ballot_sync(0xffffffffu, p[lane] > 0);
    uint32_t hi = __ballot_sync(0xffffffffu, p[32 + lane] > 0);
    if (lane == 0) g_adjbits[row * 32 + c] = make_uint2(lo, hi);
}

// ---------------------------------------------------------------------------
// Kernel A: Wh = h @ W (FFMA2 GEMM, 64 rows/block), fused:
//   - fp16 Wh^T -> g_WhT_hi [b][d][j]
//   - g_row4/g_col4 factorized exp tables
// ---------------------------------------------------------------------------
#define SMEM_A (128*128*4 + 128*PPAD*4)

__global__ __launch_bounds__(256) void wh_gemm_kernel(
    const float* __restrict__ h, const float* __restrict__ W,
    const float* __restrict__ a_src, const float* __restrict__ a_dst)
{
    extern __shared__ __align__(16) char smem_raw[];
    float* Ws = (float*)smem_raw;               // [k][d] 128x128
    float* hs = Ws + 128 * 128;                 // [k][row] 128xPPAD

    int t = threadIdx.x;
    int r0blk = blockIdx.x * 64;

    {
        const float4* src = (const float4*)W;
        float4* dst = (float4*)Ws;
#pragma unroll
        for (int q = 0; q < 16; ++q) dst[t + q * 256] = src[t + q * 256];
    }
#pragma unroll
    for (int q = 0; q < 32; ++q) {
        int idx = t + q * 256;
        int k = idx & 127, row = idx >> 7;
        hs[k * PPAD + row] = h[(size_t)(r0blk + row) * DD + k];
    }
    __syncthreads();

    int tx = t & 15, ty = t >> 4;
    int d0 = tx * 8;

    unsigned long long acc[4][4];
#pragma unroll
    for (int r = 0; r < 4; ++r)
#pragma unroll
        for (int c = 0; c < 4; ++c) acc[r][c] = 0ull;

#pragma unroll 4
    for (int k = 0; k < 128; ++k) {
        float4 hv = *(const float4*)&hs[k * PPAD + ty * 4];
        ulonglong2 w0 = *(const ulonglong2*)&Ws[k * 128 + d0];
        ulonglong2 w1 = *(const ulonglong2*)&Ws[k * 128 + d0 + 4];
        unsigned long long pp[4];
        pp[0] = pack2(hv.x, hv.x); pp[1] = pack2(hv.y, hv.y);
        pp[2] = pack2(hv.z, hv.z); pp[3] = pack2(hv.w, hv.w);
#pragma unroll
        for (int r = 0; r < 4; ++r) {
            ffma2(acc[r][0], pp[r], w0.x);
            ffma2(acc[r][1], pp[r], w0.y);
            ffma2(acc[r][2], pp[r], w1.x);
            ffma2(acc[r][3], pp[r], w1.y);
        }
    }

    float asv[8], adv[8];
    {
        float4 s0 = *(const float4*)&a_src[d0];
        float4 s1 = *(const float4*)&a_src[d0 + 4];
        float4 t0 = *(const float4*)&a_dst[d0];
        float4 t1 = *(const float4*)&a_dst[d0 + 4];
        asv[0]=s0.x; asv[1]=s0.y; asv[2]=s0.z; asv[3]=s0.w;
        asv[4]=s1.x; asv[5]=s1.y; asv[6]=s1.z; asv[7]=s1.w;
        adv[0]=t0.x; adv[1]=t0.y; adv[2]=t0.z; adv[3]=t0.w;
        adv[4]=t1.x; adv[5]=t1.y; adv[6]=t1.z; adv[7]=t1.w;
    }

#pragma unroll
    for (int r = 0; r < 4; ++r) {
        int row = r0blk + ty * 4 + r;
        float w[8];
        unpack2(w[0], w[1], acc[r][0]); unpack2(w[2], w[3], acc[r][1]);
        unpack2(w[4], w[5], acc[r][2]); unpack2(w[6], w[7], acc[r][3]);
        float sa = 0.f, sd = 0.f;
#pragma unroll
        for (int c = 0; c < 8; ++c) { sa = fmaf(w[c], asv[c], sa); sd = fmaf(w[c], adv[c], sd); }
#pragma unroll
        for (int off = 8; off > 0; off >>= 1) {
            sa += __shfl_xor_sync(0xffffffffu, sa, off);
            sd += __shfl_xor_sync(0xffffffffu, sd, off);
        }
        if (tx == 0) {
            g_row4[row] = make_float4(sa, __expf(sa), __expf(ALPHA * sa), 0.f);
            g_col4[row] = make_float4(sd, __expf(sd), __expf(ALPHA * sd), 0.f);
        }
    }

    // ---- transpose + fp16 staging (reuse hs region) ----
    __syncthreads();
    unsigned short* sthi = (unsigned short*)hs;          // [128 d][64 j]
#pragma unroll
    for (int r = 0; r < 4; ++r) {
        float w[8];
        unpack2(w[0], w[1], acc[r][0]); unpack2(w[2], w[3], acc[r][1]);
        unpack2(w[4], w[5], acc[r][2]); unpack2(w[6], w[7], acc[r][3]);
        int jl = ty * 4 + r;
#pragma unroll
        for (int c = 0; c < 8; ++c)
            sthi[(d0 + c) * 64 + jl] = __half_as_ushort(__float2half_rn(w[c]));
    }
    __syncthreads();

    int b = r0blk >> 11;
    int jblk = r0blk & (NN - 1);
    const uint4* s4h = (const uint4*)sthi;
    uint4* gh = (uint4*)g_WhT_hi;
#pragma unroll
    for (int q = 0; q < 4; ++q) {
        int idx = t + 256 * q;
        int d = idx >> 3, ch = idx & 7;
        size_t dst = (size_t)(b * DD + d) * 256 + (jblk >> 3) + ch;
        gh[dst] = s4h[idx];
    }
}

// ---------------------------------------------------------------------------
// Kernel B: warp-specialized fp16 HMMA aggregation. Grid (16, 8), 384 thr.
//  Block tile 128 i x 128 d. Warps 0-3 = producers (P fill 1 thread/row,
//  V cp.async issued ONE TILE AHEAD + wait_group 1; packed adj bitmask).
//  Warps 4-11 = consumers (2i x 4d grid, warp tile 64i x 32d).
//  3-stage pipeline for P (16KB ea) and V (16KB ea); named barriers.
// ---------------------------------------------------------------------------
#define SM_COL4 0            // 32768 B
#define SM_P    32768        // + buf*16384 (3 stages)
#define SM_V    81920        // + buf*16384 (3 stages)
#define SM_L    131072       // 128 floats
#define SMEM_B_TOTAL 131584

__global__ __launch_bounds__(384, 1) void attn_mma_kernel(float* __restrict__ out)
{
    extern __shared__ __align__(1024) char sm[];
    uint32_t smb = smem_u32(sm);
    int t = threadIdx.x, wid = t >> 5, lane = t & 31;
    int b = blockIdx.y;
    int i0 = blockIdx.x * 128;

    // col factor table for this batch (all 384 threads)
    {
        const float4* src = g_col4 + b * NN;
        float4* dst = (float4*)(sm + SM_COL4);
        for (int idx = t; idx < 2048; idx += 384) dst[idx] = src[idx];
    }
    __syncthreads();

    if (wid < 4) {
        // ======================= PRODUCER (threads 0..127) ==================
        int i = t;                                  // one thread per i-row
        float4 rv = g_row4[b * NN + i0 + i];
        float esi = rv.x, Ai = rv.y, Ci = rv.z;
        const float4* col4s = (const float4*)(sm + SM_COL4);
        const uint4* vhi_g = (const uint4*)g_WhT_hi + (size_t)b * DD * 256;
        const uint2* abrow = g_adjbits + (i0 + i) * 32;
        float lsum = 0.f;

        auto issueV = [&](int c) {
            int buf = c - (c / 3) * 3;
            uint32_t vbase = smb + SM_V + buf * 16384;
            int j8 = c * 8;
#pragma unroll
            for (int q = 0; q < 8; ++q) {
                int idx = t + 128 * q;
                int d = idx >> 3, ch = idx & 7;
                uint32_t off = SW128((uint32_t)(d * 128 + ch * 16));
                CP_ASYNC16(vbase + off, (const char*)(vhi_g + d * 256 + j8 + ch));
            }
            CP_COMMIT();
        };

        uint2 abn = __ldg(&abrow[0]);               // prefetched adj bits
        issueV(0);                                  // V(0) in flight

        for (int c = 0; c < 32; ++c) {
            int buf = c - (c / 3) * 3;              // c % 3
            if (c + 1 < 32) {
                int nb = (c + 1) - ((c + 1) / 3) * 3;
                if (c + 1 >= 3) BAR_SYNC(4 + nb);   // wait next stage empty
                issueV(c + 1);                      // V(c+1) in flight
            }
            uint2 ab = abn;
            if (c + 1 < 32) abn = __ldg(&abrow[c + 1]);

            // P row fill: row i, 64 j (bitmask select)
            char* ph = sm + SM_P + buf * 16384;
            int jb = c * 64;
#pragma unroll
            for (int hh = 0; hh < 2; ++hh) {
                uint32_t bits = hh ? ab.y : ab.x;
#pragma unroll
                for (int g = 0; g < 4; ++g) {
                    uint32_t hw[4];
#pragma unroll
                    for (int pr = 0; pr < 4; ++pr) {
                        int jj = g * 8 + pr * 2;            // 0..31 within half
                        int jg = jb + hh * 32 + jj;
                        float4 c0 = col4s[jg];
                        float4 c1 = col4s[jg + 1];
                        float s0 = esi + c0.x;
                        float s1 = esi + c1.x;
                        float v0 = (s0 > 0.f) ? Ai * c0.y : Ci * c0.z;
                        float v1 = (s1 > 0.f) ? Ai * c1.y : Ci * c1.z;
                        float p0 = ((bits >> jj) & 1u) ? v0 : 0.f;
                        float p1 = ((bits >> (jj + 1)) & 1u) ? v1 : 0.f;
                        lsum += p0 + p1;
                        __half2 hhp = __floats2half2_rn(p0, p1);
                        hw[pr] = *reinterpret_cast<uint32_t*>(&hhp);
                    }
                    uint32_t off = SW128((uint32_t)(i * 128 + hh * 64 + g * 16));
                    *(uint4*)(ph + off) = make_uint4(hw[0], hw[1], hw[2], hw[3]);
                }
            }

            if (c + 1 < 32) { CP_WAITG(1); }        // V(c) done; V(c+1) in flight
            else            { CP_WAITG(0); }
            BAR_ARRIVE(1 + buf);                    // signal stage full
        }
        ((float*)(sm + SM_L))[i] = lsum;
        BAR_ARRIVE(7);                              // join: L ready
    } else {
        // ======================= CONSUMER (threads 128..383) ================
        int cwid = wid - 4;                         // 0..7
        int wy = cwid & 1, wx = cwid >> 1;          // 2(i) x 4(d), tile 64i x 32d
        int grp = lane >> 3, lrow = lane & 7;

        float acc[4][4][4];
#pragma unroll
        for (int m = 0; m < 4; ++m)
#pragma unroll
            for (int n = 0; n < 4; ++n)
#pragma unroll
                for (int q = 0; q < 4; ++q) acc[m][n][q] = 0.f;

        for (int c = 0; c < 32; ++c) {
            int buf = c - (c / 3) * 3;              // c % 3
            BAR_SYNC(1 + buf);                      // wait stage full
            uint32_t phb = smb + SM_P + buf * 16384;
            uint32_t vhb = smb + SM_V + buf * 16384;
#pragma unroll
            for (int ks = 0; ks < 4; ++ks) {
                uint32_t ah[4][4];
#pragma unroll
                for (int mt = 0; mt < 4; ++mt) {
                    int arow = wy * 64 + mt * 16 + (grp & 1) * 8 + lrow;
                    uint32_t aoff = SW128((uint32_t)(arow * 128 + ks * 32 + (grp >> 1) * 16));
                    ldm_x4(ah[mt], phb + aoff);
                }
#pragma unroll
                for (int np = 0; np < 2; ++np) {
                    int brow = wx * 32 + np * 16 + (grp >> 1) * 8 + lrow;
                    uint32_t boff = SW128((uint32_t)(brow * 128 + ks * 32 + (grp & 1) * 16));
                    uint32_t bh[4];
                    ldm_x4(bh, vhb + boff);
#pragma unroll
                    for (int mt = 0; mt < 4; ++mt) {
                        mma_f16(acc[mt][np * 2],     ah[mt], bh);
                        mma_f16(acc[mt][np * 2 + 1], ah[mt], bh + 2);
                    }
                }
            }
            BAR_ARRIVE(4 + buf);                    // signal stage empty
        }
        BAR_SYNC(7);                                // join: wait for L

        // epilogue: scale by 1/l and store
        const float* Ls = (const float*)(sm + SM_L);
#pragma unroll
        for (int mt = 0; mt < 4; ++mt) {
            int r0 = wy * 64 + mt * 16 + (lane >> 2);
            float inv0 = 1.f / Ls[r0];
            float inv1 = 1.f / Ls[r0 + 8];
            float* orow0 = out + ((size_t)(b * NN) + i0 + r0) * DD + wx * 32 + 2 * (lane & 3);
            float* orow1 = orow0 + 8 * DD;
#pragma unroll
            for (int nt = 0; nt < 4; ++nt) {
                float2 v0; v0.x = acc[mt][nt][0] * inv0; v0.y = acc[mt][nt][1] * inv0;
                float2 v1; v1.x = acc[mt][nt][2] * inv1; v1.y = acc[mt][nt][3] * inv1;
                *(float2*)(orow0 + nt * 8) = v0;
                *(float2*)(orow1 + nt * 8) = v1;
            }
        }
    }
}

// ---------------------------------------------------------------------------
extern "C" void kernel_launch(void* const* d_in, const int* in_sizes, int n_in,
                              void* d_out, int out_size)
{
    const float* h     = (const float*)d_in[0];
    const int*   adj   = (const int*)d_in[1];
    const float* W     = (const float*)d_in[2];
    const float* a_src = (const float*)d_in[3];
    const float* a_dst = (const float*)d_in[4];
    float* out = (float*)d_out;

    cudaFuncSetAttribute(wh_gemm_kernel,  cudaFuncAttributeMaxDynamicSharedMemorySize, SMEM_A);
    cudaFuncSetAttribute(attn_mma_kernel, cudaFuncAttributeMaxDynamicSharedMemorySize, SMEM_B_TOTAL);

    pack_adj_kernel<<<8192, 256>>>(adj);
    wh_gemm_kernel<<<NB * NN / 64, 256, SMEM_A>>>(h, W, a_src, a_dst);
    attn_mma_kernel<<<dim3(NN / 128, NB), 384, SMEM_B_TOTAL>>>(out);
}